// round 3
// baseline (speedup 1.0000x reference)
#include <cuda_runtime.h>
#include <math.h>

#define B 256
#define D 128
#define T 512
#define H 256
#define C 10
#define N4 1024
#define NCTA 128
#define HPITCH 36

typedef unsigned long long u64;

// device scratch (no runtime allocation allowed)
__device__ float g_gates[(size_t)B * T * N4];   // [b][t][4H]  512 MB
__device__ float g_htp[2][H * B];               // hidden, TRANSPOSED [h][b], double buffer
__device__ unsigned g_bar;                      // grid barrier counter

__device__ __forceinline__ float sigf(float x) { return 1.0f / (1.0f + expf(-x)); }

__device__ __forceinline__ u64 pk2(float x, float y) {
    u64 r; asm("mov.b64 %0, {%1,%2};" : "=l"(r) : "f"(x), "f"(y)); return r;
}
__device__ __forceinline__ float2 upk2(u64 v) {
    float2 f; asm("mov.b64 {%0,%1}, %2;" : "=f"(f.x), "=f"(f.y) : "l"(v)); return f;
}
// d.lo += a.lo*b.lo ; d.hi += a.hi*b.hi   (packed dual fp32 FMA)
__device__ __forceinline__ void fma2(u64& d, u64 a, u64 b) {
    asm("fma.rn.f32x2 %0, %1, %2, %0;" : "+l"(d) : "l"(a), "l"(b));
}

__global__ void reset_kernel() { g_bar = 0u; }

// ---------------------------------------------------------------------------
// Proj GEMM (f32x2): gates[b][t][g*H+h] = sum_d x[b][d][t]*W[d][h] + bias
// M = B*T, N = 1024, K = 128.  128x128 tile, 8m x 8n per thread, n packed.
// ---------------------------------------------------------------------------
__global__ __launch_bounds__(256, 2) void proj_kernel(
    const float* __restrict__ x,
    const float* __restrict__ Wg, const float* __restrict__ Wi,
    const float* __restrict__ Wf, const float* __restrict__ Wo,
    const float* __restrict__ bg, const float* __restrict__ bi,
    const float* __restrict__ bf, const float* __restrict__ bo)
{
    __shared__ float As[32][128];
    __shared__ float Bs[32][128];

    const int tid = threadIdx.x;     // 256
    const int tn8 = tid & 15;
    const int tmg = tid >> 4;
    const int n0 = blockIdx.x * 128;
    const int m0 = blockIdx.y * 128;
    const int b  = m0 >> 9;          // m-tile inside one batch row (128 | 512)
    const int t0 = m0 & 511;
    const int gate = n0 >> 8;        // n-tile inside one gate (128 | 256)
    const int hb = n0 & 255;

    const float* W    = (gate == 0) ? Wg : (gate == 1) ? Wi : (gate == 2) ? Wf : Wo;
    const float* bias = (gate == 0) ? bg : (gate == 1) ? bi : (gate == 2) ? bf : bo;

    u64 acc[8][4] = {};   // [m][n-pair]; bits of (0.f,0.f) == 0ull

    for (int kc = 0; kc < 128; kc += 32) {
        __syncthreads();
        #pragma unroll
        for (int i = 0; i < 4; i++) {
            int q = tid + i * 256;
            int kk = q >> 5;
            int mq = q & 31;
            *reinterpret_cast<float4*>(&As[kk][mq * 4]) =
                *reinterpret_cast<const float4*>(&x[(size_t)b * (D * T) + (kc + kk) * T + t0 + mq * 4]);
            *reinterpret_cast<float4*>(&Bs[kk][mq * 4]) =
                *reinterpret_cast<const float4*>(&W[(kc + kk) * H + hb + mq * 4]);
        }
        __syncthreads();

        #pragma unroll
        for (int kk = 0; kk < 32; kk++) {
            float a[8];
            *reinterpret_cast<float4*>(&a[0]) = *reinterpret_cast<float4*>(&As[kk][tmg * 8]);
            *reinterpret_cast<float4*>(&a[4]) = *reinterpret_cast<float4*>(&As[kk][tmg * 8 + 4]);
            ulonglong2 bq0 = *reinterpret_cast<const ulonglong2*>(&Bs[kk][tn8 * 8]);
            ulonglong2 bq1 = *reinterpret_cast<const ulonglong2*>(&Bs[kk][tn8 * 8 + 4]);
            #pragma unroll
            for (int mi = 0; mi < 8; mi++) {
                u64 ad = pk2(a[mi], a[mi]);
                fma2(acc[mi][0], ad, bq0.x);
                fma2(acc[mi][1], ad, bq0.y);
                fma2(acc[mi][2], ad, bq1.x);
                fma2(acc[mi][3], ad, bq1.y);
            }
        }
    }

    float bv[8];
    #pragma unroll
    for (int ni = 0; ni < 8; ni++) bv[ni] = bias[hb + tn8 * 8 + ni];

    #pragma unroll
    for (int mi = 0; mi < 8; mi++) {
        size_t m = (size_t)(m0 + tmg * 8 + mi);
        float2 c0 = upk2(acc[mi][0]);
        float2 c1 = upk2(acc[mi][1]);
        float2 c2 = upk2(acc[mi][2]);
        float2 c3 = upk2(acc[mi][3]);
        float4 v0 = make_float4(c0.x + bv[0], c0.y + bv[1], c1.x + bv[2], c1.y + bv[3]);
        float4 v1 = make_float4(c2.x + bv[4], c2.y + bv[5], c3.x + bv[6], c3.y + bv[7]);
        *reinterpret_cast<float4*>(&g_gates[m * N4 + n0 + tn8 * 8])     = v0;
        *reinterpret_cast<float4*>(&g_gates[m * N4 + n0 + tn8 * 8 + 4]) = v1;
    }
}

// ---------------------------------------------------------------------------
// Persistent LSTM recurrence (f32x2).
// Grid (16 h-tiles, 8 b-tiles) = 128 CTAs, 128 threads each, all co-resident.
// CTA tile: 32 b x 16 h x 4 gates.  Thread: tx = tid&15 (h), tb = tid>>4
// (owns 4 consecutive b).  W slice lives in smem PRE-DUPLICATED (w,w) so the
// packed inner loop needs zero per-iteration packing:
//   per k: 1 LDS.128 (4 h-values = 2 b-pairs) + 2 LDS.128 (4 dup gates)
//          + 8 FFMA2  (= 16 FMAs).
// h is kept TRANSPOSED in global ([h][b]) so staging needs no smem transpose.
// ---------------------------------------------------------------------------
#define WDUP_FLOATS (256 * 16 * 4 * 2)          // 32768 floats = 128 KB
#define SMEM_LSTM   ((WDUP_FLOATS + 256 * HPITCH) * 4)

__global__ __launch_bounds__(128, 1) void lstm_kernel(
    const float* __restrict__ Wg, const float* __restrict__ Wi,
    const float* __restrict__ Wf, const float* __restrict__ Wo)
{
    extern __shared__ float sm[];
    float* wdup = sm;                      // [k][tx][gate] float2(w,w)
    float* hs   = sm + WDUP_FLOATS;        // [k][HPITCH] : h values for 32 b

    const int tid = threadIdx.x;           // 128
    const int tx = tid & 15;               // h-local
    const int tb = tid >> 4;               // 0..7 (4 b each)
    const int h0 = blockIdx.x * 16;
    const int b0 = blockIdx.y * 32;
    const int hh = h0 + tx;
    const int bb = b0 + tb * 4;

    // Build duplicated weight slice once: entry idx = (k*16 + tx)*4 + g
    for (int idx = tid; idx < 16384; idx += 128) {
        int k = idx >> 6;
        int r = idx & 63;
        int xx = r >> 2;
        int g = r & 3;
        const float* W = (g == 0) ? Wg : (g == 1) ? Wi : (g == 2) ? Wf : Wo;
        float w = W[k * H + h0 + xx];
        reinterpret_cast<float2*>(wdup)[idx] = make_float2(w, w);
    }
    __syncthreads();

    const float* wbase = wdup + tx * 8;     // float offset: (k*16+tx)*4*2 = k*128 + tx*8
    float cst[4] = {0.f, 0.f, 0.f, 0.f};

    for (int t = 0; t < T; t++) {
        // prefetch gate pre-activations (hides DRAM behind GEMM)
        float pre[4][4];
        #pragma unroll
        for (int j = 0; j < 4; j++) {
            size_t base = ((size_t)(bb + j) * T + t) * N4 + hh;
            pre[j][0] = __ldcg(&g_gates[base]);
            pre[j][1] = __ldcg(&g_gates[base + 256]);
            pre[j][2] = __ldcg(&g_gates[base + 512]);
            pre[j][3] = __ldcg(&g_gates[base + 768]);
        }

        u64 acc[2][4] = {};   // [b-pair][gate]

        if (t > 0) {
            const float* rbuf = g_htp[(t + 1) & 1];
            // stage h^T: 256 k-rows x 32 b = 2048 float4, 16 per thread, coalesced
            #pragma unroll
            for (int i = 0; i < 16; i++) {
                int idx = tid + i * 128;
                int k = idx >> 3;
                int f4 = idx & 7;
                float4 v = __ldcg(reinterpret_cast<const float4*>(&rbuf[k * B + b0 + f4 * 4]));
                *reinterpret_cast<float4*>(&hs[k * HPITCH + f4 * 4]) = v;
            }
            __syncthreads();

            #pragma unroll 8
            for (int kk = 0; kk < 256; kk++) {
                ulonglong2 hq = *reinterpret_cast<const ulonglong2*>(&hs[kk * HPITCH + tb * 4]);
                const ulonglong2* wp = reinterpret_cast<const ulonglong2*>(wbase + kk * 128);
                ulonglong2 w01 = wp[0];   // (g0,g0),(g1,g1)
                ulonglong2 w23 = wp[1];   // (g2,g2),(g3,g3)
                fma2(acc[0][0], hq.x, w01.x);
                fma2(acc[0][1], hq.x, w01.y);
                fma2(acc[0][2], hq.x, w23.x);
                fma2(acc[0][3], hq.x, w23.y);
                fma2(acc[1][0], hq.y, w01.x);
                fma2(acc[1][1], hq.y, w01.y);
                fma2(acc[1][2], hq.y, w23.x);
                fma2(acc[1][3], hq.y, w23.y);
            }
        }

        // pointwise LSTM update; c stays in registers
        float hv[4];
        #pragma unroll
        for (int p = 0; p < 2; p++) {
            float2 ag = upk2(acc[p][0]);
            float2 ai = upk2(acc[p][1]);
            float2 af = upk2(acc[p][2]);
            float2 ao = upk2(acc[p][3]);
            float aG[2] = {ag.x, ag.y}, aI[2] = {ai.x, ai.y};
            float aF[2] = {af.x, af.y}, aO[2] = {ao.x, ao.y};
            #pragma unroll
            for (int e = 0; e < 2; e++) {
                int j = p * 2 + e;
                float gv = tanhf(pre[j][0] + aG[e]);
                float iv = sigf (pre[j][1] + aI[e]);
                float fv = sigf (pre[j][2] + aF[e]);
                float ov = sigf (pre[j][3] + aO[e]);
                float cc = gv * iv + cst[j] * fv;
                cst[j] = cc;
                hv[j] = tanhf(cc) * ov;
            }
        }
        __stcg(reinterpret_cast<float4*>(&g_htp[t & 1][hh * B + bb]),
               make_float4(hv[0], hv[1], hv[2], hv[3]));

        // grid barrier (all 128 CTAs co-resident)
        __syncthreads();
        if (tid == 0) {
            __threadfence();
            atomicAdd(&g_bar, 1u);
            unsigned need = (unsigned)NCTA * (unsigned)(t + 1);
            while (*(volatile unsigned*)&g_bar < need) __nanosleep(32);
        }
        __syncthreads();
    }
}

// ---------------------------------------------------------------------------
// Head: out[b][c] = h_final[b][:] @ W_ph[:,c] + b_p[c]; h stored as [h][b].
// ---------------------------------------------------------------------------
__global__ void final_kernel(const float* __restrict__ Wp,
                             const float* __restrict__ bp,
                             float* __restrict__ out)
{
    __shared__ float hsm[H];
    int b = blockIdx.x;
    hsm[threadIdx.x] = g_htp[(T - 1) & 1][threadIdx.x * B + b];
    __syncthreads();
    if (threadIdx.x < C) {
        float acc = bp[threadIdx.x];
        #pragma unroll 8
        for (int k = 0; k < H; k++)
            acc += hsm[k] * Wp[k * C + threadIdx.x];
        out[b * C + threadIdx.x] = acc;
    }
}

// ---------------------------------------------------------------------------
extern "C" void kernel_launch(void* const* d_in, const int* in_sizes, int n_in,
                              void* d_out, int out_size)
{
    const float* x    = (const float*)d_in[0];
    const float* W_gx = (const float*)d_in[1];
    const float* W_ix = (const float*)d_in[2];
    const float* W_fx = (const float*)d_in[3];
    const float* W_ox = (const float*)d_in[4];
    const float* W_gh = (const float*)d_in[5];
    const float* W_ih = (const float*)d_in[6];
    const float* W_fh = (const float*)d_in[7];
    const float* W_oh = (const float*)d_in[8];
    const float* b_g  = (const float*)d_in[9];
    const float* b_i  = (const float*)d_in[10];
    const float* b_f  = (const float*)d_in[11];
    const float* b_o  = (const float*)d_in[12];
    const float* W_ph = (const float*)d_in[13];
    const float* b_p  = (const float*)d_in[14];
    float* out = (float*)d_out;

    static bool attr_set = false;
    if (!attr_set) {
        cudaFuncSetAttribute(lstm_kernel,
                             cudaFuncAttributeMaxDynamicSharedMemorySize, SMEM_LSTM);
        attr_set = true;
    }

    reset_kernel<<<1, 1>>>();

    proj_kernel<<<dim3(N4 / 128, (B * T) / 128), 256>>>(
        x, W_gx, W_ix, W_fx, W_ox, b_g, b_i, b_f, b_o);

    lstm_kernel<<<dim3(H / 16, B / 32), 128, SMEM_LSTM>>>(W_gh, W_ih, W_fh, W_oh);

    final_kernel<<<B, H>>>(W_ph, b_p, out);
}

// round 5
// speedup vs baseline: 2.1663x; 2.1663x over previous
#include <cuda_runtime.h>
#include <cuda_bf16.h>
#include <math.h>
#include <stdint.h>

#define B 256
#define D 128
#define T 512
#define H 256
#define C 10
#define N4 1024

// device scratch (no runtime allocation allowed)
__device__ float g_gates[(size_t)B * T * N4];        // [b][t][4H] fp32, 512 MB
__device__ unsigned short g_hhi[2][B * H];           // h bf16 hi, [b][k], dbl-buffered
__device__ unsigned short g_hlo[2][B * H];           // h bf16 lo
__device__ float g_hfin[B * H];                      // final h fp32
__device__ unsigned g_bar4[4];                       // per-m-group barriers

__device__ __forceinline__ float sigf(float x) { return 1.0f / (1.0f + expf(-x)); }

__global__ void reset_kernel() {
    if (threadIdx.x < 4) g_bar4[threadIdx.x] = 0u;
}

__device__ __forceinline__ uint32_t smem_u32(const void* p) {
    uint32_t a;
    asm("{ .reg .u64 t; cvta.to.shared.u64 t, %1; cvt.u32.u64 %0, t; }" : "=r"(a) : "l"(p));
    return a;
}
__device__ __forceinline__ void ldmx4(uint32_t& r0, uint32_t& r1, uint32_t& r2,
                                      uint32_t& r3, uint32_t addr) {
    asm volatile("ldmatrix.sync.aligned.m8n8.x4.shared.b16 {%0,%1,%2,%3}, [%4];"
                 : "=r"(r0), "=r"(r1), "=r"(r2), "=r"(r3) : "r"(addr));
}
__device__ __forceinline__ void mma16816(float& c0, float& c1, float& c2, float& c3,
                                         uint32_t a0, uint32_t a1, uint32_t a2, uint32_t a3,
                                         uint32_t b0, uint32_t b1) {
    asm volatile(
        "mma.sync.aligned.m16n8k16.row.col.f32.bf16.bf16.f32 "
        "{%0,%1,%2,%3}, {%4,%5,%6,%7}, {%8,%9}, {%0,%1,%2,%3};"
        : "+f"(c0), "+f"(c1), "+f"(c2), "+f"(c3)
        : "r"(a0), "r"(a1), "r"(a2), "r"(a3), "r"(b0), "r"(b1));
}

// smem byte layout (row pitch 528 B = 264 bf16 -> conflict-free ldmatrix)
#define APITCHB 528
#define OFF_AHI 0
#define OFF_ALO (OFF_AHI + 64 * APITCHB)     // 33792
#define OFF_BHI (OFF_ALO + 64 * APITCHB)     // 67584
#define OFF_BLO (OFF_BHI + 32 * APITCHB)     // 84480
#define OFF_CX  (OFF_BLO + 32 * APITCHB)     // 101376
#define CXP 34
#define SMEM_LSTM (OFF_CX + 64 * CXP * 4)    // 110080 bytes

// ---------------------------------------------------------------------------
// Proj GEMM (fp32, proven): gates[b][t][g*H+h] = sum_d x[b][d][t]*W[d][h]+bias
// ---------------------------------------------------------------------------
__global__ __launch_bounds__(256, 2) void proj_kernel(
    const float* __restrict__ x,
    const float* __restrict__ Wg, const float* __restrict__ Wi,
    const float* __restrict__ Wf, const float* __restrict__ Wo,
    const float* __restrict__ bg, const float* __restrict__ bi,
    const float* __restrict__ bf, const float* __restrict__ bo)
{
    __shared__ float As[32][128];
    __shared__ float Bs[32][128];

    const int tid = threadIdx.x;
    const int tn8 = tid & 15;
    const int tmg = tid >> 4;
    const int n0 = blockIdx.x * 128;
    const int m0 = blockIdx.y * 128;
    const int b  = m0 >> 9;
    const int t0 = m0 & 511;
    const int gate = n0 >> 8;
    const int hb = n0 & 255;

    const float* W    = (gate == 0) ? Wg : (gate == 1) ? Wi : (gate == 2) ? Wf : Wo;
    const float* bias = (gate == 0) ? bg : (gate == 1) ? bi : (gate == 2) ? bf : bo;

    float acc[8][8] = {};

    for (int kc = 0; kc < 128; kc += 32) {
        __syncthreads();
        #pragma unroll
        for (int i = 0; i < 4; i++) {
            int q = tid + i * 256;
            int kk = q >> 5;
            int mq = q & 31;
            *reinterpret_cast<float4*>(&As[kk][mq * 4]) =
                *reinterpret_cast<const float4*>(&x[(size_t)b * (D * T) + (kc + kk) * T + t0 + mq * 4]);
            *reinterpret_cast<float4*>(&Bs[kk][mq * 4]) =
                *reinterpret_cast<const float4*>(&W[(kc + kk) * H + hb + mq * 4]);
        }
        __syncthreads();

        #pragma unroll
        for (int kk = 0; kk < 32; kk++) {
            float a[8], bb[8];
            *reinterpret_cast<float4*>(&a[0])  = *reinterpret_cast<float4*>(&As[kk][tmg * 8]);
            *reinterpret_cast<float4*>(&a[4])  = *reinterpret_cast<float4*>(&As[kk][tmg * 8 + 4]);
            *reinterpret_cast<float4*>(&bb[0]) = *reinterpret_cast<float4*>(&Bs[kk][tn8 * 8]);
            *reinterpret_cast<float4*>(&bb[4]) = *reinterpret_cast<float4*>(&Bs[kk][tn8 * 8 + 4]);
            #pragma unroll
            for (int mi = 0; mi < 8; mi++)
                #pragma unroll
                for (int ni = 0; ni < 8; ni++)
                    acc[mi][ni] += a[mi] * bb[ni];
        }
    }

    float bv[8];
    #pragma unroll
    for (int ni = 0; ni < 8; ni++) bv[ni] = bias[hb + tn8 * 8 + ni];

    #pragma unroll
    for (int mi = 0; mi < 8; mi++) {
        size_t m = (size_t)(m0 + tmg * 8 + mi);
        float4 v0 = make_float4(acc[mi][0] + bv[0], acc[mi][1] + bv[1],
                                acc[mi][2] + bv[2], acc[mi][3] + bv[3]);
        float4 v1 = make_float4(acc[mi][4] + bv[4], acc[mi][5] + bv[5],
                                acc[mi][6] + bv[6], acc[mi][7] + bv[7]);
        *reinterpret_cast<float4*>(&g_gates[m * N4 + n0 + tn8 * 8])     = v0;
        *reinterpret_cast<float4*>(&g_gates[m * N4 + n0 + tn8 * 8 + 4]) = v1;
    }
}

// ---------------------------------------------------------------------------
// Persistent LSTM recurrence on mma.sync (bf16 hi/lo 3-pass, fp32 accum).
// Grid (32 nb, 4 gm) = 128 CTAs, 256 threads (8 warps), 1 CTA/SM.
// CTA tile: 64 b x 32 n (4 gates x 8 h), K = 256.
// Warp w: wm = w&3 (16 m rows), nq = w>>2 (16 n cols).
// ---------------------------------------------------------------------------
__global__ __launch_bounds__(256, 1) void lstm_kernel(
    const float* __restrict__ Wg, const float* __restrict__ Wi,
    const float* __restrict__ Wf, const float* __restrict__ Wo)
{
    extern __shared__ char sm[];
    const uint32_t sb = smem_u32(sm);
    float* Cx = reinterpret_cast<float*>(sm + OFF_CX);

    const int tid = threadIdx.x;
    const int lane = tid & 31;
    const int w = tid >> 5;
    const int wm = w & 3;
    const int nq = w >> 2;
    const int nb = blockIdx.x;        // 0..31
    const int gm = blockIdx.y;        // 0..3
    const int hb8 = nb * 8;

    // Build W tile bf16 hi/lo in smem once: B[n][k], n = g*8+hl
    for (int idx = tid; idx < 32 * 256; idx += 256) {
        int k = idx >> 5;
        int n = idx & 31;
        int g = n >> 3, hl = n & 7;
        const float* W = (g == 0) ? Wg : (g == 1) ? Wi : (g == 2) ? Wf : Wo;
        float wv = W[k * H + hb8 + hl];
        __nv_bfloat16 bh = __float2bfloat16(wv);
        __nv_bfloat16 bl = __float2bfloat16(wv - __bfloat162float(bh));
        *reinterpret_cast<unsigned short*>(sm + OFF_BHI + n * APITCHB + k * 2) =
            reinterpret_cast<unsigned short&>(bh);
        *reinterpret_cast<unsigned short*>(sm + OFF_BLO + n * APITCHB + k * 2) =
            reinterpret_cast<unsigned short&>(bl);
    }
    __syncthreads();

    // ldmatrix lane addresses (byte offsets inside tile)
    const uint32_t a_row = wm * 16 + (lane & 7) + ((lane >> 3) & 1) * 8;
    const uint32_t a_base = a_row * APITCHB + (lane >> 4) * 16;          // + kk*32
    const uint32_t b_row = nq * 16 + (lane >> 4) * 8 + (lane & 7);
    const uint32_t b_base = b_row * APITCHB + ((lane >> 3) & 1) * 16;    // + kk*32

    // pointwise ownership: 2 h-values per thread
    const int bl_ = tid >> 2;                 // b-local 0..63
    const int hl2 = (tid & 3) * 2;            // h-local pair
    const int bglob = gm * 64 + bl_;

    float2 cstate = make_float2(0.f, 0.f);

    for (int t = 0; t < T; t++) {
        // prefetch gate pre-activations (independent of h)
        float2 pg, pi_, pf_, po;
        {
            const size_t rb = ((size_t)bglob * T + t) * N4 + hb8 + hl2;
            pg  = __ldcg(reinterpret_cast<const float2*>(&g_gates[rb]));
            pi_ = __ldcg(reinterpret_cast<const float2*>(&g_gates[rb + 256]));
            pf_ = __ldcg(reinterpret_cast<const float2*>(&g_gates[rb + 512]));
            po  = __ldcg(reinterpret_cast<const float2*>(&g_gates[rb + 768]));
        }

        float2 ag = make_float2(0.f, 0.f), ai = ag, af = ag, ao = ag;

        if (t > 0) {
            // wait for our m-group's h(t-1)
            __syncthreads();
            if (tid == 0) {
                while (*(volatile unsigned*)&g_bar4[gm] < (unsigned)(32 * t))
                    __nanosleep(32);
            }
            __syncthreads();

            // stage A = h(t-1) rows [gm*64, +64), bf16 hi/lo
            const unsigned short* src_hi = g_hhi[(t + 1) & 1];
            const unsigned short* src_lo = g_hlo[(t + 1) & 1];
            #pragma unroll
            for (int i = 0; i < 8; i++) {
                int idx = tid + i * 256;
                int m = idx >> 5;
                int ch = idx & 31;
                size_t gidx = (size_t)(gm * 64 + m) * H + ch * 8;
                uint4 vh = __ldcg(reinterpret_cast<const uint4*>(&src_hi[gidx]));
                uint4 vl = __ldcg(reinterpret_cast<const uint4*>(&src_lo[gidx]));
                *reinterpret_cast<uint4*>(sm + OFF_AHI + m * APITCHB + ch * 16) = vh;
                *reinterpret_cast<uint4*>(sm + OFF_ALO + m * APITCHB + ch * 16) = vl;
            }
            __syncthreads();

            // 3-pass split MMA over K = 256 (16 k-steps)
            float c0[4] = {0.f, 0.f, 0.f, 0.f};   // n-block 0
            float c1[4] = {0.f, 0.f, 0.f, 0.f};   // n-block 1
            #pragma unroll
            for (int kk = 0; kk < 16; kk++) {
                uint32_t ah0, ah1, ah2, ah3, al0, al1, al2, al3;
                uint32_t bh0, bh1, bh2, bh3, bl0, bl1, bl2, bl3;
                ldmx4(ah0, ah1, ah2, ah3, sb + OFF_AHI + a_base + kk * 32);
                ldmx4(al0, al1, al2, al3, sb + OFF_ALO + a_base + kk * 32);
                ldmx4(bh0, bh1, bh2, bh3, sb + OFF_BHI + b_base + kk * 32);
                ldmx4(bl0, bl1, bl2, bl3, sb + OFF_BLO + b_base + kk * 32);
                mma16816(c0[0], c0[1], c0[2], c0[3], ah0, ah1, ah2, ah3, bh0, bh1);
                mma16816(c0[0], c0[1], c0[2], c0[3], al0, al1, al2, al3, bh0, bh1);
                mma16816(c0[0], c0[1], c0[2], c0[3], ah0, ah1, ah2, ah3, bl0, bl1);
                mma16816(c1[0], c1[1], c1[2], c1[3], ah0, ah1, ah2, ah3, bh2, bh3);
                mma16816(c1[0], c1[1], c1[2], c1[3], al0, al1, al2, al3, bh2, bh3);
                mma16816(c1[0], c1[1], c1[2], c1[3], ah0, ah1, ah2, ah3, bl2, bl3);
            }

            // exchange C through smem: Cx[m-local][n-local]
            {
                int crow = wm * 16 + (lane >> 2);
                int ccol = nq * 16 + (lane & 3) * 2;
                *reinterpret_cast<float2*>(&Cx[crow * CXP + ccol]) =
                    make_float2(c0[0], c0[1]);
                *reinterpret_cast<float2*>(&Cx[(crow + 8) * CXP + ccol]) =
                    make_float2(c0[2], c0[3]);
                *reinterpret_cast<float2*>(&Cx[crow * CXP + ccol + 8]) =
                    make_float2(c1[0], c1[1]);
                *reinterpret_cast<float2*>(&Cx[(crow + 8) * CXP + ccol + 8]) =
                    make_float2(c1[2], c1[3]);
            }
            __syncthreads();

            ag = *reinterpret_cast<float2*>(&Cx[bl_ * CXP + 0 * 8 + hl2]);
            ai = *reinterpret_cast<float2*>(&Cx[bl_ * CXP + 1 * 8 + hl2]);
            af = *reinterpret_cast<float2*>(&Cx[bl_ * CXP + 2 * 8 + hl2]);
            ao = *reinterpret_cast<float2*>(&Cx[bl_ * CXP + 3 * 8 + hl2]);
        }

        // pointwise LSTM update (2 h-values per thread, c in registers)
        float hx = tanhf(pg.x + ag.x);
        float hy = tanhf(pg.y + ag.y);
        float ix = sigf(pi_.x + ai.x);
        float iy = sigf(pi_.y + ai.y);
        float fx = sigf(pf_.x + af.x);
        float fy = sigf(pf_.y + af.y);
        float ox = sigf(po.x + ao.x);
        float oy = sigf(po.y + ao.y);
        cstate.x = hx * ix + cstate.x * fx;
        cstate.y = hy * iy + cstate.y * fy;
        float h0 = tanhf(cstate.x) * ox;
        float h1 = tanhf(cstate.y) * oy;

        if (t < T - 1) {
            __nv_bfloat16 b0 = __float2bfloat16(h0);
            __nv_bfloat16 b1 = __float2bfloat16(h1);
            __nv_bfloat16 l0 = __float2bfloat16(h0 - __bfloat162float(b0));
            __nv_bfloat16 l1 = __float2bfloat16(h1 - __bfloat162float(b1));
            unsigned uhi = (unsigned)reinterpret_cast<unsigned short&>(b0) |
                           ((unsigned)reinterpret_cast<unsigned short&>(b1) << 16);
            unsigned ulo = (unsigned)reinterpret_cast<unsigned short&>(l0) |
                           ((unsigned)reinterpret_cast<unsigned short&>(l1) << 16);
            size_t hidx = (size_t)bglob * H + hb8 + hl2;
            __stcg(reinterpret_cast<unsigned*>(&g_hhi[t & 1][hidx]), uhi);
            __stcg(reinterpret_cast<unsigned*>(&g_hlo[t & 1][hidx]), ulo);
            __threadfence();
            __syncthreads();
            if (tid == 0) atomicAdd(&g_bar4[gm], 1u);
        } else {
            *reinterpret_cast<float2*>(&g_hfin[(size_t)bglob * H + hb8 + hl2]) =
                make_float2(h0, h1);
        }
    }
}

// ---------------------------------------------------------------------------
// Head: out[b][c] = h_final[b][:] @ W_ph[:,c] + b_p[c]
// ---------------------------------------------------------------------------
__global__ void final_kernel(const float* __restrict__ Wp,
                             const float* __restrict__ bp,
                             float* __restrict__ out)
{
    __shared__ float hsm[H];
    int b = blockIdx.x;
    hsm[threadIdx.x] = g_hfin[b * H + threadIdx.x];
    __syncthreads();
    if (threadIdx.x < C) {
        float acc = bp[threadIdx.x];
        #pragma unroll 8
        for (int k = 0; k < H; k++)
            acc += hsm[k] * Wp[k * C + threadIdx.x];
        out[b * C + threadIdx.x] = acc;
    }
}

// ---------------------------------------------------------------------------
extern "C" void kernel_launch(void* const* d_in, const int* in_sizes, int n_in,
                              void* d_out, int out_size)
{
    const float* x    = (const float*)d_in[0];
    const float* W_gx = (const float*)d_in[1];
    const float* W_ix = (const float*)d_in[2];
    const float* W_fx = (const float*)d_in[3];
    const float* W_ox = (const float*)d_in[4];
    const float* W_gh = (const float*)d_in[5];
    const float* W_ih = (const float*)d_in[6];
    const float* W_fh = (const float*)d_in[7];
    const float* W_oh = (const float*)d_in[8];
    const float* b_g  = (const float*)d_in[9];
    const float* b_i  = (const float*)d_in[10];
    const float* b_f  = (const float*)d_in[11];
    const float* b_o  = (const float*)d_in[12];
    const float* W_ph = (const float*)d_in[13];
    const float* b_p  = (const float*)d_in[14];
    float* out = (float*)d_out;

    static bool attr_set = false;
    if (!attr_set) {
        cudaFuncSetAttribute(lstm_kernel,
                             cudaFuncAttributeMaxDynamicSharedMemorySize, SMEM_LSTM);
        attr_set = true;
    }

    reset_kernel<<<1, 32>>>();

    proj_kernel<<<dim3(N4 / 128, (B * T) / 128), 256>>>(
        x, W_gx, W_ix, W_fx, W_ox, b_g, b_i, b_f, b_o);

    lstm_kernel<<<dim3(32, 4), 256, SMEM_LSTM>>>(W_gh, W_ih, W_fh, W_oh);

    final_kernel<<<B, H>>>(W_ph, b_p, out);
}

// round 6
// speedup vs baseline: 2.7523x; 1.2705x over previous
#include <cuda_runtime.h>
#include <cuda_bf16.h>
#include <math.h>
#include <stdint.h>

#define B 256
#define D 128
#define T 512
#define H 256
#define C 10
#define N4 1024

// device scratch (no runtime allocation allowed)
__device__ float g_gates[(size_t)B * T * N4];        // [b][t][4H] fp32, 512 MB
__device__ unsigned short g_hhi[2][B * H];           // h bf16 hi, [b][k], dbl-buffered
__device__ unsigned short g_hlo[2][B * H];           // h bf16 lo
__device__ float g_hfin[B * H];                      // final h fp32
__device__ unsigned g_bar4[4];                       // per-m-group barriers

__device__ __forceinline__ float sigf(float x) { return 1.0f / (1.0f + expf(-x)); }

__global__ void reset_kernel() {
    if (threadIdx.x < 4) g_bar4[threadIdx.x] = 0u;
}

__device__ __forceinline__ uint32_t smem_u32(const void* p) {
    uint32_t a;
    asm("{ .reg .u64 t; cvta.to.shared.u64 t, %1; cvt.u32.u64 %0, t; }" : "=r"(a) : "l"(p));
    return a;
}
__device__ __forceinline__ void ldmx4(uint32_t& r0, uint32_t& r1, uint32_t& r2,
                                      uint32_t& r3, uint32_t addr) {
    asm volatile("ldmatrix.sync.aligned.m8n8.x4.shared.b16 {%0,%1,%2,%3}, [%4];"
                 : "=r"(r0), "=r"(r1), "=r"(r2), "=r"(r3) : "r"(addr));
}
__device__ __forceinline__ void ldmx4t(uint32_t* r, uint32_t addr) {
    asm volatile("ldmatrix.sync.aligned.m8n8.x4.trans.shared.b16 {%0,%1,%2,%3}, [%4];"
                 : "=r"(r[0]), "=r"(r[1]), "=r"(r[2]), "=r"(r[3]) : "r"(addr));
}
__device__ __forceinline__ void mma16816(float* c,
                                         uint32_t a0, uint32_t a1, uint32_t a2, uint32_t a3,
                                         uint32_t b0, uint32_t b1) {
    asm volatile(
        "mma.sync.aligned.m16n8k16.row.col.f32.bf16.bf16.f32 "
        "{%0,%1,%2,%3}, {%4,%5,%6,%7}, {%8,%9}, {%0,%1,%2,%3};"
        : "+f"(c[0]), "+f"(c[1]), "+f"(c[2]), "+f"(c[3])
        : "r"(a0), "r"(a1), "r"(a2), "r"(a3), "r"(b0), "r"(b1));
}
__device__ __forceinline__ uint32_t pkbf(float x, float y) {
    __nv_bfloat16 a = __float2bfloat16(x), b = __float2bfloat16(y);
    return (uint32_t)reinterpret_cast<unsigned short&>(a) |
           ((uint32_t)reinterpret_cast<unsigned short&>(b) << 16);
}

// ============================== PROJ (mma) ==================================
// gates[b][t][g*H+h] = sum_d x[b][d][t]*W[d][h] + bias.  M=B*T, N=1024, K=128.
// CTA tile 128m x 128n, bf16 hi/lo 3-pass, A:[k][m] B:[k][n] trans-ldmatrix.
#define PPITCH 272                        // 17*16 bytes per k-row
#define P_AHI 0
#define P_ALO (128 * PPITCH)
#define P_BHI (2 * 128 * PPITCH)
#define P_BLO (3 * 128 * PPITCH)
#define SMEM_PROJ (4 * 128 * PPITCH)      // 139264 B

__global__ __launch_bounds__(256, 1) void projmma_kernel(
    const float* __restrict__ x,
    const float* __restrict__ Wg, const float* __restrict__ Wi,
    const float* __restrict__ Wf, const float* __restrict__ Wo,
    const float* __restrict__ bg, const float* __restrict__ bi,
    const float* __restrict__ bf, const float* __restrict__ bo)
{
    extern __shared__ char psm[];
    const uint32_t sb = smem_u32(psm);

    const int tid = threadIdx.x;
    const int lane = tid & 31;
    const int w = tid >> 5;
    const int wm2 = w & 3;            // 32-m slice
    const int nq2 = w >> 2;           // 64-n slice
    const int n0 = blockIdx.x * 128;
    const int m0 = blockIdx.y * 128;
    const int b  = m0 >> 9;
    const int t0 = m0 & 511;
    const int gate = n0 >> 8;
    const int hb = n0 & 255;

    const float* W    = (gate == 0) ? Wg : (gate == 1) ? Wi : (gate == 2) ? Wf : Wo;
    const float* bias = (gate == 0) ? bg : (gate == 1) ? bi : (gate == 2) ? bf : bo;

    // load + convert x and W tiles into hi/lo bf16 smem ([k][m] / [k][n])
    #pragma unroll
    for (int i = 0; i < 16; i++) {
        int q = tid + i * 256;        // 0..4095
        int k = q >> 5;
        int m4 = q & 31;
        float4 v = __ldcg(reinterpret_cast<const float4*>(
            &x[(size_t)b * (D * T) + k * T + t0 + m4 * 4]));
        float4 wv = __ldg(reinterpret_cast<const float4*>(&W[k * H + hb + m4 * 4]));
        uint32_t hiA0 = pkbf(v.x, v.y), hiA1 = pkbf(v.z, v.w);
        float rx = v.x - __bfloat162float(__float2bfloat16(v.x));
        float ry = v.y - __bfloat162float(__float2bfloat16(v.y));
        float rz = v.z - __bfloat162float(__float2bfloat16(v.z));
        float rw = v.w - __bfloat162float(__float2bfloat16(v.w));
        uint32_t loA0 = pkbf(rx, ry), loA1 = pkbf(rz, rw);
        uint32_t hiB0 = pkbf(wv.x, wv.y), hiB1 = pkbf(wv.z, wv.w);
        float sx = wv.x - __bfloat162float(__float2bfloat16(wv.x));
        float sy = wv.y - __bfloat162float(__float2bfloat16(wv.y));
        float sz = wv.z - __bfloat162float(__float2bfloat16(wv.z));
        float sw = wv.w - __bfloat162float(__float2bfloat16(wv.w));
        uint32_t loB0 = pkbf(sx, sy), loB1 = pkbf(sz, sw);
        uint32_t off = k * PPITCH + m4 * 8;
        *reinterpret_cast<uint2*>(psm + P_AHI + off) = make_uint2(hiA0, hiA1);
        *reinterpret_cast<uint2*>(psm + P_ALO + off) = make_uint2(loA0, loA1);
        *reinterpret_cast<uint2*>(psm + P_BHI + off) = make_uint2(hiB0, hiB1);
        *reinterpret_cast<uint2*>(psm + P_BLO + off) = make_uint2(loB0, loB1);
    }
    __syncthreads();

    // trans-ldmatrix lane address offsets
    const int sel = lane >> 3;        // 0..3
    const int lr  = lane & 7;
    // A frag (m16k16): r0=(m0-7,k0-7) r1=(m8-15,k0-7) r2=(m0-7,k8-15) r3=(m8-15,k8-15)
    const uint32_t aoff = (uint32_t)(((sel >> 1) * 8 + lr) * PPITCH + (sel & 1) * 16);
    // B frag (n16k16): r0=(n0-7,k0-7) r1=(n0-7,k8-15) r2=(n8-15,k0-7) r3=(n8-15,k8-15)
    const uint32_t boff = (uint32_t)(((sel & 1) * 8 + lr) * PPITCH + (sel >> 1) * 16);

    float acc[2][8][4] = {};          // [m-frag][n8][4]

    #pragma unroll
    for (int kk = 0; kk < 8; kk++) {
        const uint32_t kb = kk * 16 * PPITCH;
        uint32_t ah[2][4], al[2][4], bh[4][4], bl[4][4];
        #pragma unroll
        for (int mf = 0; mf < 2; mf++) {
            uint32_t mcol = (wm2 * 32 + mf * 16) * 2;
            ldmx4t(ah[mf], sb + P_AHI + kb + aoff + mcol);
            ldmx4t(al[mf], sb + P_ALO + kb + aoff + mcol);
        }
        #pragma unroll
        for (int ng = 0; ng < 4; ng++) {
            uint32_t ncol = (nq2 * 64 + ng * 16) * 2;
            ldmx4t(bh[ng], sb + P_BHI + kb + boff + ncol);
            ldmx4t(bl[ng], sb + P_BLO + kb + boff + ncol);
        }
        #pragma unroll
        for (int mf = 0; mf < 2; mf++) {
            #pragma unroll
            for (int ng = 0; ng < 4; ng++) {
                float* c0 = acc[mf][ng * 2];
                float* c1 = acc[mf][ng * 2 + 1];
                mma16816(c0, ah[mf][0], ah[mf][1], ah[mf][2], ah[mf][3], bh[ng][0], bh[ng][1]);
                mma16816(c0, al[mf][0], al[mf][1], al[mf][2], al[mf][3], bh[ng][0], bh[ng][1]);
                mma16816(c0, ah[mf][0], ah[mf][1], ah[mf][2], ah[mf][3], bl[ng][0], bl[ng][1]);
                mma16816(c1, ah[mf][0], ah[mf][1], ah[mf][2], ah[mf][3], bh[ng][2], bh[ng][3]);
                mma16816(c1, al[mf][0], al[mf][1], al[mf][2], al[mf][3], bh[ng][2], bh[ng][3]);
                mma16816(c1, ah[mf][0], ah[mf][1], ah[mf][2], ah[mf][3], bl[ng][2], bl[ng][3]);
            }
        }
    }

    // epilogue: c0,c1 -> row lane>>2, c2,c3 -> row+8; cols (lane&3)*2
    #pragma unroll
    for (int mf = 0; mf < 2; mf++) {
        int m = m0 + wm2 * 32 + mf * 16 + (lane >> 2);
        #pragma unroll
        for (int j = 0; j < 8; j++) {
            int hcol = hb + nq2 * 64 + j * 8 + (lane & 3) * 2;
            float2 bv = *reinterpret_cast<const float2*>(&bias[hcol]);
            int ncol = gate * 256 + hcol;
            *reinterpret_cast<float2*>(&g_gates[(size_t)m * N4 + ncol]) =
                make_float2(acc[mf][j][0] + bv.x, acc[mf][j][1] + bv.y);
            *reinterpret_cast<float2*>(&g_gates[(size_t)(m + 8) * N4 + ncol]) =
                make_float2(acc[mf][j][2] + bv.x, acc[mf][j][3] + bv.y);
        }
    }
}

// ============================ RECURRENCE ====================================
#define APITCHB 528
#define OFF_AHI 0
#define OFF_ALO (OFF_AHI + 64 * APITCHB)
#define OFF_BHI (OFF_ALO + 64 * APITCHB)
#define OFF_BLO (OFF_BHI + 32 * APITCHB)
#define OFF_CX  (OFF_BLO + 32 * APITCHB)
#define CXP 34
#define SMEM_LSTM (OFF_CX + 64 * CXP * 4)

__global__ __launch_bounds__(256, 1) void lstm_kernel(
    const float* __restrict__ Wg, const float* __restrict__ Wi,
    const float* __restrict__ Wf, const float* __restrict__ Wo)
{
    extern __shared__ char sm[];
    const uint32_t sb = smem_u32(sm);
    float* Cx = reinterpret_cast<float*>(sm + OFF_CX);

    const int tid = threadIdx.x;
    const int lane = tid & 31;
    const int w = tid >> 5;
    const int wm = w & 3;
    const int nq = w >> 2;
    const int nb = blockIdx.x;        // 0..31
    const int gm = blockIdx.y;        // 0..3
    const int hb8 = nb * 8;

    // Build W tile bf16 hi/lo in smem once: B[n][k], n = g*8+hl
    for (int idx = tid; idx < 32 * 256; idx += 256) {
        int k = idx >> 5;
        int n = idx & 31;
        int g = n >> 3, hl = n & 7;
        const float* W = (g == 0) ? Wg : (g == 1) ? Wi : (g == 2) ? Wf : Wo;
        float wv = W[k * H + hb8 + hl];
        __nv_bfloat16 bh = __float2bfloat16(wv);
        __nv_bfloat16 bl = __float2bfloat16(wv - __bfloat162float(bh));
        *reinterpret_cast<unsigned short*>(sm + OFF_BHI + n * APITCHB + k * 2) =
            reinterpret_cast<unsigned short&>(bh);
        *reinterpret_cast<unsigned short*>(sm + OFF_BLO + n * APITCHB + k * 2) =
            reinterpret_cast<unsigned short&>(bl);
    }
    __syncthreads();

    const uint32_t a_row = wm * 16 + (lane & 7) + ((lane >> 3) & 1) * 8;
    const uint32_t a_base = a_row * APITCHB + (lane >> 4) * 16;
    const uint32_t b_row = nq * 16 + (lane >> 4) * 8 + (lane & 7);
    const uint32_t b_base = b_row * APITCHB + ((lane >> 3) & 1) * 16;

    const int bl_ = tid >> 2;
    const int hl2 = (tid & 3) * 2;
    const int bglob = gm * 64 + bl_;

    float2 cstate = make_float2(0.f, 0.f);

    for (int t = 0; t < T; t++) {
        float2 pg, pi_, pf_, po;
        {
            const size_t rb = ((size_t)bglob * T + t) * N4 + hb8 + hl2;
            pg  = __ldcg(reinterpret_cast<const float2*>(&g_gates[rb]));
            pi_ = __ldcg(reinterpret_cast<const float2*>(&g_gates[rb + 256]));
            pf_ = __ldcg(reinterpret_cast<const float2*>(&g_gates[rb + 512]));
            po  = __ldcg(reinterpret_cast<const float2*>(&g_gates[rb + 768]));
        }

        float2 ag = make_float2(0.f, 0.f), ai = ag, af = ag, ao = ag;

        if (t > 0) {
            __syncthreads();
            if (tid == 0) {
                unsigned need = (unsigned)(32 * t);
                unsigned v;
                do {
                    asm volatile("ld.acquire.gpu.global.u32 %0, [%1];"
                                 : "=r"(v) : "l"(&g_bar4[gm]) : "memory");
                } while (v < need);
            }
            __syncthreads();

            const unsigned short* src_hi = g_hhi[(t + 1) & 1];
            const unsigned short* src_lo = g_hlo[(t + 1) & 1];
            #pragma unroll
            for (int i = 0; i < 8; i++) {
                int idx = tid + i * 256;
                int m = idx >> 5;
                int ch = idx & 31;
                size_t gidx = (size_t)(gm * 64 + m) * H + ch * 8;
                uint4 vh = __ldcg(reinterpret_cast<const uint4*>(&src_hi[gidx]));
                uint4 vl = __ldcg(reinterpret_cast<const uint4*>(&src_lo[gidx]));
                *reinterpret_cast<uint4*>(sm + OFF_AHI + m * APITCHB + ch * 16) = vh;
                *reinterpret_cast<uint4*>(sm + OFF_ALO + m * APITCHB + ch * 16) = vl;
            }
            __syncthreads();

            float c0[4] = {0.f, 0.f, 0.f, 0.f};
            float c1[4] = {0.f, 0.f, 0.f, 0.f};
            #pragma unroll
            for (int kk = 0; kk < 16; kk++) {
                uint32_t ah[4], al[4], bh[4], blx[4];
                ldmx4(ah[0], ah[1], ah[2], ah[3], sb + OFF_AHI + a_base + kk * 32);
                ldmx4(al[0], al[1], al[2], al[3], sb + OFF_ALO + a_base + kk * 32);
                ldmx4(bh[0], bh[1], bh[2], bh[3], sb + OFF_BHI + b_base + kk * 32);
                ldmx4(blx[0], blx[1], blx[2], blx[3], sb + OFF_BLO + b_base + kk * 32);
                mma16816(c0, ah[0], ah[1], ah[2], ah[3], bh[0], bh[1]);
                mma16816(c0, al[0], al[1], al[2], al[3], bh[0], bh[1]);
                mma16816(c0, ah[0], ah[1], ah[2], ah[3], blx[0], blx[1]);
                mma16816(c1, ah[0], ah[1], ah[2], ah[3], bh[2], bh[3]);
                mma16816(c1, al[0], al[1], al[2], al[3], bh[2], bh[3]);
                mma16816(c1, ah[0], ah[1], ah[2], ah[3], blx[2], blx[3]);
            }

            {
                int crow = wm * 16 + (lane >> 2);
                int ccol = nq * 16 + (lane & 3) * 2;
                *reinterpret_cast<float2*>(&Cx[crow * CXP + ccol]) = make_float2(c0[0], c0[1]);
                *reinterpret_cast<float2*>(&Cx[(crow + 8) * CXP + ccol]) = make_float2(c0[2], c0[3]);
                *reinterpret_cast<float2*>(&Cx[crow * CXP + ccol + 8]) = make_float2(c1[0], c1[1]);
                *reinterpret_cast<float2*>(&Cx[(crow + 8) * CXP + ccol + 8]) = make_float2(c1[2], c1[3]);
            }
            __syncthreads();

            ag = *reinterpret_cast<float2*>(&Cx[bl_ * CXP + 0 * 8 + hl2]);
            ai = *reinterpret_cast<float2*>(&Cx[bl_ * CXP + 1 * 8 + hl2]);
            af = *reinterpret_cast<float2*>(&Cx[bl_ * CXP + 2 * 8 + hl2]);
            ao = *reinterpret_cast<float2*>(&Cx[bl_ * CXP + 3 * 8 + hl2]);
        }

        float hx = tanhf(pg.x + ag.x);
        float hy = tanhf(pg.y + ag.y);
        float ix = sigf(pi_.x + ai.x);
        float iy = sigf(pi_.y + ai.y);
        float fx = sigf(pf_.x + af.x);
        float fy = sigf(pf_.y + af.y);
        float ox = sigf(po.x + ao.x);
        float oy = sigf(po.y + ao.y);
        cstate.x = hx * ix + cstate.x * fx;
        cstate.y = hy * iy + cstate.y * fy;
        float h0 = tanhf(cstate.x) * ox;
        float h1 = tanhf(cstate.y) * oy;

        if (t < T - 1) {
            unsigned uhi = pkbf(h0, h1);
            __nv_bfloat16 q0 = __float2bfloat16(h0);
            __nv_bfloat16 q1 = __float2bfloat16(h1);
            unsigned ulo = pkbf(h0 - __bfloat162float(q0), h1 - __bfloat162float(q1));
            size_t hidx = (size_t)bglob * H + hb8 + hl2;
            __stcg(reinterpret_cast<unsigned*>(&g_hhi[t & 1][hidx]), uhi);
            __stcg(reinterpret_cast<unsigned*>(&g_hlo[t & 1][hidx]), ulo);
            __syncthreads();
            if (tid == 0) {
                asm volatile("red.release.gpu.global.add.u32 [%0], %1;"
                             :: "l"(&g_bar4[gm]), "r"(1u) : "memory");
            }
        } else {
            *reinterpret_cast<float2*>(&g_hfin[(size_t)bglob * H + hb8 + hl2]) =
                make_float2(h0, h1);
        }
    }
}

// ================================ HEAD ======================================
__global__ void final_kernel(const float* __restrict__ Wp,
                             const float* __restrict__ bp,
                             float* __restrict__ out)
{
    __shared__ float hsm[H];
    int b = blockIdx.x;
    hsm[threadIdx.x] = g_hfin[b * H + threadIdx.x];
    __syncthreads();
    if (threadIdx.x < C) {
        float acc = bp[threadIdx.x];
        #pragma unroll 8
        for (int k = 0; k < H; k++)
            acc += hsm[k] * Wp[k * C + threadIdx.x];
        out[b * C + threadIdx.x] = acc;
    }
}

// ---------------------------------------------------------------------------
extern "C" void kernel_launch(void* const* d_in, const int* in_sizes, int n_in,
                              void* d_out, int out_size)
{
    const float* x    = (const float*)d_in[0];
    const float* W_gx = (const float*)d_in[1];
    const float* W_ix = (const float*)d_in[2];
    const float* W_fx = (const float*)d_in[3];
    const float* W_ox = (const float*)d_in[4];
    const float* W_gh = (const float*)d_in[5];
    const float* W_ih = (const float*)d_in[6];
    const float* W_fh = (const float*)d_in[7];
    const float* W_oh = (const float*)d_in[8];
    const float* b_g  = (const float*)d_in[9];
    const float* b_i  = (const float*)d_in[10];
    const float* b_f  = (const float*)d_in[11];
    const float* b_o  = (const float*)d_in[12];
    const float* W_ph = (const float*)d_in[13];
    const float* b_p  = (const float*)d_in[14];
    float* out = (float*)d_out;

    static bool attr_set = false;
    if (!attr_set) {
        cudaFuncSetAttribute(lstm_kernel,
                             cudaFuncAttributeMaxDynamicSharedMemorySize, SMEM_LSTM);
        cudaFuncSetAttribute(projmma_kernel,
                             cudaFuncAttributeMaxDynamicSharedMemorySize, SMEM_PROJ);
        attr_set = true;
    }

    reset_kernel<<<1, 32>>>();

    projmma_kernel<<<dim3(N4 / 128, (B * T) / 128), 256, SMEM_PROJ>>>(
        x, W_gx, W_ix, W_fx, W_ox, b_g, b_i, b_f, b_o);

    lstm_kernel<<<dim3(32, 4), 256, SMEM_LSTM>>>(W_gh, W_ih, W_fh, W_oh);

    final_kernel<<<B, H>>>(W_ph, b_p, out);
}